// round 7
// baseline (speedup 1.0000x reference)
#include <cuda_runtime.h>

#define B 128
#define DF 2048
#define KSPLIT 8
#define KCHUNK 256          // DF / KSPLIT
#define SUB 64              // k sub-chunk held in SMEM
#define NSUB 4              // KCHUNK / SUB
#define NBLOCKS 128
#define NTHREADS 256
#define LDP 34              // padded SMEM row (float2-aligned, conflict-free)
#define BUF_FLOATS (SUB * LDP)          // one As or Bs buffer: 2176 floats

// Scratch (static device globals; no allocation).
__device__ float g_Gp[KSPLIT * B * B];   // split-K partial Gram (512KB)
__device__ float g_diagP[KSPLIT * B];    // diag partials per layer
__device__ float g_part[NBLOCKS];        // per-block loss partials
__device__ unsigned g_bar;               // monotonic barrier counter (never reset)
__device__ unsigned g_fin;               // monotonic finalize counter (never reset)

// Monotonic grid barrier: no reset across graph replays (2^32 % 128 == 0).
__device__ __forceinline__ void grid_barrier() {
    __syncthreads();
    if (threadIdx.x == 0) {
        __threadfence();                                   // release
        unsigned old = atomicAdd(&g_bar, 1u);
        unsigned target = old - (old & (NBLOCKS - 1u)) + NBLOCKS;
        while ((int)(*(volatile unsigned*)&g_bar - target) < 0) {
            __nanosleep(64);
        }
        __threadfence();                                   // acquire
    }
    __syncthreads();
}

// Sum one G entry over all 8 split-K layers (fixed order -> deterministic).
__device__ __forceinline__ float rowsum8(int row, int k) {
    float s = 0.f;
#pragma unroll
    for (int z = 0; z < KSPLIT; z++)
        s += __ldcg(&g_Gp[z * (B * B) + row * B + k]);
    return s;
}

__global__ __launch_bounds__(NTHREADS) void fused_angle_loss(
    const float* __restrict__ X, float* __restrict__ out) {

    __shared__ float smemBuf[4 * BUF_FLOATS];   // 2 k-buffers x (As+Bs) = 34.8KB
    const int b = blockIdx.x;
    const int t = threadIdx.x;

    // ============================ Phase 1: split-K Gram =====================
    // block b: z = b>>4 (K chunk of 256), tile = b&15 -> 32x32 output tile.
    // Software-pipelined over 4 sub-chunks of 64 k (double-buffered SMEM).
    {
        const int z  = b >> 4;
        const int tr = ((b >> 2) & 3) * 32;
        const int tc = (b & 3) * 32;
        const int kZ = z * KCHUNK;

        const int row = t >> 4;            // 0..15 -> used twice (it loop)
        const int kq  = (t & 15) * 4;      // k offset within sub-chunk

        const int r0 = (t >> 4) * 2;       // micro-tile row (0..30 even)
        const int c0 = (t & 15) * 2;       // micro-tile col

        float4 aR[2], bR[2];

        // prologue: load sub-chunk 0
        {
            const int kb = kZ;
#pragma unroll
            for (int it = 0; it < 2; it++) {
                const int rr = row + it * 16;            // 0..31
                aR[it] = *(const float4*)(X + (size_t)(tr + rr) * DF + kb + kq);
                bR[it] = *(const float4*)(X + (size_t)(tc + rr) * DF + kb + kq);
            }
        }
        {
            float* As = smemBuf;
            float* Bs = smemBuf + BUF_FLOATS;
#pragma unroll
            for (int it = 0; it < 2; it++) {
                const int rr = row + it * 16;
                As[(kq + 0) * LDP + rr] = aR[it].x; As[(kq + 1) * LDP + rr] = aR[it].y;
                As[(kq + 2) * LDP + rr] = aR[it].z; As[(kq + 3) * LDP + rr] = aR[it].w;
                Bs[(kq + 0) * LDP + rr] = bR[it].x; Bs[(kq + 1) * LDP + rr] = bR[it].y;
                Bs[(kq + 2) * LDP + rr] = bR[it].z; Bs[(kq + 3) * LDP + rr] = bR[it].w;
            }
        }
        __syncthreads();

        float acc00 = 0.f, acc01 = 0.f, acc10 = 0.f, acc11 = 0.f;

#pragma unroll
        for (int cc = 0; cc < NSUB; cc++) {
            // prefetch next sub-chunk while computing on current
            if (cc < NSUB - 1) {
                const int kb = kZ + (cc + 1) * SUB;
#pragma unroll
                for (int it = 0; it < 2; it++) {
                    const int rr = row + it * 16;
                    aR[it] = *(const float4*)(X + (size_t)(tr + rr) * DF + kb + kq);
                    bR[it] = *(const float4*)(X + (size_t)(tc + rr) * DF + kb + kq);
                }
            }

            const float* As = smemBuf + (cc & 1) * 2 * BUF_FLOATS;
            const float* Bs = As + BUF_FLOATS;
#pragma unroll 16
            for (int k = 0; k < SUB; k++) {
                float2 a = *(const float2*)&As[k * LDP + r0];
                float2 bv = *(const float2*)&Bs[k * LDP + c0];
                acc00 = fmaf(a.x, bv.x, acc00);
                acc01 = fmaf(a.x, bv.y, acc01);
                acc10 = fmaf(a.y, bv.x, acc10);
                acc11 = fmaf(a.y, bv.y, acc11);
            }

            if (cc < NSUB - 1) {
                float* As2 = smemBuf + ((cc + 1) & 1) * 2 * BUF_FLOATS;
                float* Bs2 = As2 + BUF_FLOATS;
#pragma unroll
                for (int it = 0; it < 2; it++) {
                    const int rr = row + it * 16;
                    As2[(kq + 0) * LDP + rr] = aR[it].x; As2[(kq + 1) * LDP + rr] = aR[it].y;
                    As2[(kq + 2) * LDP + rr] = aR[it].z; As2[(kq + 3) * LDP + rr] = aR[it].w;
                    Bs2[(kq + 0) * LDP + rr] = bR[it].x; Bs2[(kq + 1) * LDP + rr] = bR[it].y;
                    Bs2[(kq + 2) * LDP + rr] = bR[it].z; Bs2[(kq + 3) * LDP + rr] = bR[it].w;
                }
                __syncthreads();
            }
        }

        // writeback 2x2 micro-tile
        float* dst = g_Gp + z * (B * B);
        *(float2*)&dst[(tr + r0) * B + tc + c0]     = make_float2(acc00, acc01);
        *(float2*)&dst[(tr + r0 + 1) * B + tc + c0] = make_float2(acc10, acc11);

        // diag partials (only diagonal tiles; threads on the micro-diagonal)
        if (tr == tc && (t >> 4) == (t & 15)) {
            g_diagP[z * B + tr + r0]     = acc00;
            g_diagP[z * B + tr + r0 + 1] = acc11;
        }
    }

    grid_barrier();

    // ================ Phase 2+3 fused: reduce + loss (128 blocks) ===========
    // b = group*8 + slice. Group g=(target,sub); slice s -> pairs
    // (j0,j1) = (16p+s, 16p+s+8). Each block reduces exactly the G rows it
    // needs across the 8 split-K layers (fixed order -> deterministic).
    {
        const int g    = b >> 3;
        const int s    = b & 7;
        const int tgt  = g >> 1;
        const int sb   = g & 1;
        const int base = tgt * 16 + sb * 8;
        const int k    = t & 127;
        const int h    = t >> 7;

        float* sS0  = smemBuf;           // [128] partial S (rows base..base+3)
        float* sS1  = smemBuf + 128;     // [128] partial S (rows base+4..+7)
        float* sSf  = smemBuf + 256;     // [128] final S/8
        float* sInv = smemBuf + 384;     // [128] 1/norm
        float* sDg  = smemBuf + 512;     // [128] diag
        float* red  = smemBuf + 640;     // [8]
        int* sFlag  = (int*)(smemBuf + 648);

        // ---- z-reduced loads (independent bursts) ----
        float sp0 = rowsum8(base + h * 4 + 0, k);
        float sp1 = rowsum8(base + h * 4 + 1, k);
        float sp2 = rowsum8(base + h * 4 + 2, k);
        float sp3 = rowsum8(base + h * 4 + 3, k);

        float gv0[4], gv1[4];
#pragma unroll
        for (int pi = 0; pi < 4; pi++) {
            const int p  = h * 4 + pi;
            const int j0 = p * 16 + s;
            gv0[pi] = rowsum8(j0, k);          // loaded even if p==tgt
            gv1[pi] = rowsum8(j0 + 8, k);
        }

        float dsum = 0.f;
        if (h == 1) {
#pragma unroll
            for (int z = 0; z < KSPLIT; z++) dsum += __ldcg(&g_diagP[z * B + k]);
        }
        __syncthreads();    // smem reuse guard (phase-1 buffers done)

        const float sp = ((sp0 + sp1) + (sp2 + sp3));
        if (h == 0) sS0[k] = sp;
        else { sS1[k] = sp; sDg[k] = dsum; }
        __syncthreads();

        if (h == 0) sSf[k] = (sS0[k] + sS1[k]) * 0.125f;
        __syncthreads();

        float q = 0.f;
#pragma unroll
        for (int i = 0; i < 8; i++) q += sSf[base + i];
        q *= 0.125f;

        if (h == 0) {
            const float n2 = sDg[k] - 2.f * sSf[k] + q;
            const float nr = sqrtf(fmaxf(n2, 0.f));
            sInv[k] = 1.f / fmaxf(nr, 1e-12f);
        }
        __syncthreads();

        const float sk   = sSf[k];
        const float invk = sInv[k];
        float acc = 0.f;
#pragma unroll
        for (int pi = 0; pi < 4; pi++) {
            const int p = h * 4 + pi;
            if (p == tgt) continue;
            const int j0 = p * 16 + s;
            const int j1 = j0 + 8;
            const float a0 = (gv0[pi] - sSf[j0] - sk + q) * (sInv[j0] * invk);
            const float a1 = (gv1[pi] - sSf[j1] - sk + q) * (sInv[j1] * invk);
            acc += fabsf(a0 - a1);
        }

        // Deterministic block reduction over 256 threads.
#pragma unroll
        for (int o = 16; o > 0; o >>= 1) acc += __shfl_down_sync(0xffffffffu, acc, o);
        if ((t & 31) == 0) red[t >> 5] = acc;
        __syncthreads();

        if (t == 0) {
            float sum = 0.f;
#pragma unroll
            for (int w = 0; w < 8; w++) sum += red[w];
            g_part[b] = sum;
            __threadfence();
            unsigned old = atomicAdd(&g_fin, 1u);
            sFlag[0] = ((old & (NBLOCKS - 1u)) == (NBLOCKS - 1u)) ? 1 : 0;
        }
        __syncthreads();

        // ---- parallel deterministic finalize by the last-arriving block ----
        if (sFlag[0]) {
            float v = (t < NBLOCKS) ? __ldcg(&g_part[t]) : 0.f;
#pragma unroll
            for (int o = 16; o > 0; o >>= 1) v += __shfl_down_sync(0xffffffffu, v, o);
            if ((t & 31) == 0) red[t >> 5] = v;
            __syncthreads();
            if (t == 0) {
                float tot = ((red[0] + red[1]) + (red[2] + red[3]));
                out[0] = tot * (1.0f / 114688.0f);
            }
        }
    }
}

extern "C" void kernel_launch(void* const* d_in, const int* in_sizes, int n_in,
                              void* d_out, int out_size) {
    const float* X = (const float*)d_in[0];   // [128, 2048] fp32
    float* out = (float*)d_out;               // scalar loss

    fused_angle_loss<<<NBLOCKS, NTHREADS>>>(X, out);
}

// round 8
// speedup vs baseline: 1.0869x; 1.0869x over previous
#include <cuda_runtime.h>

#define B 128
#define DF 2048
#define KSPLIT 32
#define KCHUNK 64           // DF / KSPLIT
#define NBLOCKS 128
#define NTHREADS 512

// Scratch (static device globals; no allocation).
__device__ float g_Gp[KSPLIT * B * B];   // split-K partial Gram
__device__ float g_G[B * B];             // reduced Gram
__device__ float g_part[NBLOCKS];        // per-block loss partials
__device__ unsigned g_bar[2];            // monotonic barrier counters (never reset)
__device__ unsigned g_fin;               // monotonic finalize counter (never reset)

// Monotonic grid barrier: no reset across graph replays (2^32 % 128 == 0).
__device__ __forceinline__ void grid_barrier(int which) {
    __syncthreads();
    if (threadIdx.x == 0) {
        __threadfence();                                   // release
        unsigned old = atomicAdd(&g_bar[which], 1u);
        unsigned target = old - (old & (NBLOCKS - 1u)) + NBLOCKS;
        while ((int)(*(volatile unsigned*)&g_bar[which] - target) < 0) {
            __nanosleep(64);
        }
        __threadfence();                                   // acquire
    }
    __syncthreads();
}

__global__ __launch_bounds__(NTHREADS) void fused_angle_loss(
    const float* __restrict__ X, float* __restrict__ out) {

    __shared__ float smemBuf[2 * KCHUNK * 68];   // 34.8KB, reused across phases
    const int b = blockIdx.x;
    const int t = threadIdx.x;

    // ============================ Phase 1: split-K Gram =====================
    // block b: z = b>>2 (K chunk), tile index b&3 -> 64x64 output tile.
    // 512 threads, 2x4 micro-tile each: high occupancy hides LDS/L2 latency.
    {
        const int z     = b >> 2;
        const int tileR = ((b >> 1) & 1) * 64;
        const int tileC = (b & 1) * 64;
        const int kBase = z * KCHUNK;

        float (*As)[68] = (float(*)[68])smemBuf;
        float (*Bs)[68] = (float(*)[68])(smemBuf + KCHUNK * 68);

        // Load A,B: 64 rows x 64 k = 1024 float4 each; 2 per thread. k-major.
#pragma unroll
        for (int it = 0; it < 2; it++) {
            const int i   = t + it * NTHREADS;      // 0..1023
            const int row = i >> 4;                 // 0..63
            const int kq  = (i & 15) * 4;           // 0..60
            float4 va = *(const float4*)(X + (size_t)(tileR + row) * DF + kBase + kq);
            As[kq + 0][row] = va.x; As[kq + 1][row] = va.y;
            As[kq + 2][row] = va.z; As[kq + 3][row] = va.w;
            float4 vb = *(const float4*)(X + (size_t)(tileC + row) * DF + kBase + kq);
            Bs[kq + 0][row] = vb.x; Bs[kq + 1][row] = vb.y;
            Bs[kq + 2][row] = vb.z; Bs[kq + 3][row] = vb.w;
        }
        __syncthreads();

        const int r0 = (t >> 4) * 2;               // 0..62 (even)
        const int c0 = (t & 15) * 4;               // 0..60
        float acc[2][4] = {};
#pragma unroll 16
        for (int k = 0; k < KCHUNK; k++) {
            float2 a  = *(const float2*)&As[k][r0];
            float4 bv = *(const float4*)&Bs[k][c0];
            acc[0][0] = fmaf(a.x, bv.x, acc[0][0]);
            acc[0][1] = fmaf(a.x, bv.y, acc[0][1]);
            acc[0][2] = fmaf(a.x, bv.z, acc[0][2]);
            acc[0][3] = fmaf(a.x, bv.w, acc[0][3]);
            acc[1][0] = fmaf(a.y, bv.x, acc[1][0]);
            acc[1][1] = fmaf(a.y, bv.y, acc[1][1]);
            acc[1][2] = fmaf(a.y, bv.z, acc[1][2]);
            acc[1][3] = fmaf(a.y, bv.w, acc[1][3]);
        }

        float* dst = g_Gp + (size_t)z * (B * B);
#pragma unroll
        for (int ii = 0; ii < 2; ii++) {
            float4 v = make_float4(acc[ii][0], acc[ii][1], acc[ii][2], acc[ii][3]);
            *(float4*)&dst[(tileR + r0 + ii) * B + tileC + c0] = v;
        }
    }

    grid_barrier(0);

    // ===================== Phase 2: split-K reduce (all 128 blocks) =========
    // 4096 float4 outputs / 128 blocks = 32 per block. 512 threads:
    // thread t: f4 = t&31, z-group = t>>5 (0..15) sums 2 layers; then t<32
    // combines the 16 partials in fixed order (deterministic).
    {
        float4* part = (float4*)smemBuf;           // [16][32] float4
        const int f4c = t & 31;
        const int zg  = t >> 5;
        const int f4  = b * 32 + f4c;
        const float4* src = (const float4*)g_Gp;
        float4 s0 = __ldcg(src + (size_t)(zg * 2 + 0) * 4096 + f4);
        float4 s1 = __ldcg(src + (size_t)(zg * 2 + 1) * 4096 + f4);
        s0.x += s1.x; s0.y += s1.y; s0.z += s1.z; s0.w += s1.w;
        part[zg * 32 + f4c] = s0;
        __syncthreads();
        if (t < 32) {
            float4 r = part[t];
#pragma unroll
            for (int zg2 = 1; zg2 < 16; zg2++) {
                float4 v = part[zg2 * 32 + t];
                r.x += v.x; r.y += v.y; r.z += v.z; r.w += v.w;
            }
            ((float4*)g_G)[f4] = r;
        }
    }

    grid_barrier(1);

    // ======================= Phase 3: loss (all 128 blocks) =================
    // b = group*8 + slice. Group g=(target,sub); slice s -> pairs
    // (j0,j1) = (16p+s, 16p+s+8) for the 7 p != target.
    // 512 threads: k = t&127, quarter h = t>>7 (0..3). h0/h1 split the 8
    // S-rows, h2 loads diag, each h loads 2 p-pairs. One L2 round total.
    {
        const int g    = b >> 3;
        const int s    = b & 7;
        const int tgt  = g >> 1;
        const int sb   = g & 1;
        const int base = tgt * 16 + sb * 8;
        const int k    = t & 127;
        const int h    = t >> 7;

        float* sS0  = smemBuf;           // [128] S partial rows 0..3
        float* sS1  = smemBuf + 128;     // [128] S partial rows 4..7
        float* sSf  = smemBuf + 256;     // [128] final S/8
        float* sInv = smemBuf + 384;     // [128] 1/norm
        float* sDg  = smemBuf + 512;     // [128] diag
        float* red  = smemBuf + 640;     // [16]
        int* sFlag  = (int*)(smemBuf + 656);

        // ---- batched loads (independent; one MLP window) ----
        float rowv[4] = {0.f, 0.f, 0.f, 0.f};
        float dia = 0.f;
        if (h < 2) {
#pragma unroll
            for (int i = 0; i < 4; i++)
                rowv[i] = __ldcg(&g_G[(base + h * 4 + i) * B + k]);
        } else if (h == 2) {
            dia = __ldcg(&g_G[k * B + k]);
        }
        float gv0[2], gv1[2];
#pragma unroll
        for (int pi = 0; pi < 2; pi++) {
            const int p  = h * 2 + pi;
            const int j0 = p * 16 + s;
            gv0[pi] = __ldcg(&g_G[j0 * B + k]);         // loaded even if p==tgt
            gv1[pi] = __ldcg(&g_G[(j0 + 8) * B + k]);
        }
        __syncthreads();    // phase-2 smem reads complete before overwrite

        if (h == 0) sS0[k] = (rowv[0] + rowv[1]) + (rowv[2] + rowv[3]);
        else if (h == 1) sS1[k] = (rowv[0] + rowv[1]) + (rowv[2] + rowv[3]);
        else if (h == 2) sDg[k] = dia;
        __syncthreads();

        if (h == 0) sSf[k] = (sS0[k] + sS1[k]) * 0.125f;
        __syncthreads();

        float q = 0.f;
#pragma unroll
        for (int i = 0; i < 8; i++) q += sSf[base + i];
        q *= 0.125f;

        if (h == 0) {
            const float n2 = sDg[k] - 2.f * sSf[k] + q;
            const float nr = sqrtf(fmaxf(n2, 0.f));
            sInv[k] = 1.f / fmaxf(nr, 1e-12f);
        }
        __syncthreads();

        const float sk   = sSf[k];
        const float invk = sInv[k];
        float acc = 0.f;
#pragma unroll
        for (int pi = 0; pi < 2; pi++) {
            const int p = h * 2 + pi;
            if (p == tgt) continue;
            const int j0 = p * 16 + s;
            const int j1 = j0 + 8;
            const float a0 = (gv0[pi] - sSf[j0] - sk + q) * (sInv[j0] * invk);
            const float a1 = (gv1[pi] - sSf[j1] - sk + q) * (sInv[j1] * invk);
            acc += fabsf(a0 - a1);
        }

        // Deterministic block reduction over 512 threads (16 warps).
#pragma unroll
        for (int o = 16; o > 0; o >>= 1) acc += __shfl_down_sync(0xffffffffu, acc, o);
        if ((t & 31) == 0) red[t >> 5] = acc;
        __syncthreads();

        if (t == 0) {
            float sum = 0.f;
#pragma unroll
            for (int w = 0; w < 16; w++) sum += red[w];
            g_part[b] = sum;
            __threadfence();
            unsigned old = atomicAdd(&g_fin, 1u);
            sFlag[0] = ((old & (NBLOCKS - 1u)) == (NBLOCKS - 1u)) ? 1 : 0;
        }
        __syncthreads();

        // ---- parallel deterministic finalize by the last-arriving block ----
        if (sFlag[0]) {
            float v = (t < NBLOCKS) ? __ldcg(&g_part[t]) : 0.f;
#pragma unroll
            for (int o = 16; o > 0; o >>= 1) v += __shfl_down_sync(0xffffffffu, v, o);
            if ((t & 31) == 0) red[t >> 5] = v;
            __syncthreads();
            if (t == 0) {
                float tot = ((red[0] + red[1]) + (red[2] + red[3]));
                out[0] = tot * (1.0f / 114688.0f);
            }
        }
    }
}

extern "C" void kernel_launch(void* const* d_in, const int* in_sizes, int n_in,
                              void* d_out, int out_size) {
    const float* X = (const float*)d_in[0];   // [128, 2048] fp32
    float* out = (float*)d_out;               // scalar loss

    fused_angle_loss<<<NBLOCKS, NTHREADS>>>(X, out);
}